// round 16
// baseline (speedup 1.0000x reference)
#include <cuda_runtime.h>
#include <cuda_bf16.h>
#include <math.h>

// Problem constants
#define Bsz   512
#define NA    8
#define OB    160
#define SD    256
#define NH    4
#define GD    64
#define KD    65
#define NU    32
#define Ntot  4096
#define KDSQ  4225

// Output layout (flat concat, fp32)
#define OUT_ATTN  512
#define OUT_DENSE 16896
#define DENSE_F4  16777216ULL

#define PP 68              // g_part2 pitch

// kB geometry
#define NKG    13
#define KPG    5
#define NTIL   32
#define OPAD   168         // padded o-dim (336B rows)
#define NJ     72          // padded j-dim (j=64 real, 65..71 zero)
#define SLABB  48384       // one k B slab BYTES
#define TERMB  24192       // one B term (72 j x 336B)
#define ATERM  43008       // one A term (128 rows x 336B)
#define GRIDB  (NKG * NTIL)   // 416
// kB smem: A [0,86016) | B double buffer [86016,182784) | keys | bias
#define SM_B    86016
#define SM_KEYS 182784
#define SM_BIAS 185344
#define SM_TOT  186880

// zero-fill split: kAP covers [0, Z_SPLIT), kB covers the rest
#define ZAP_THREADS 92448ULL          // 321 * 288
#define ZAP_PER     68
#define Z_SPLIT     (ZAP_THREADS * ZAP_PER)   // 6286464 < DENSE_F4

#define CPA16(dst, src) asm volatile("cp.async.cg.shared.global [%0], [%1], 16;" :: "r"(dst), "l"(src))
#define CPA_COMMIT() asm volatile("cp.async.commit_group;")
#define CPA_WAIT(n)  asm volatile("cp.async.wait_group %0;" :: "n"(n))
#define MMA(C, A, b0, b1) \
    asm volatile("mma.sync.aligned.m16n8k16.row.col.f32.bf16.bf16.f32 " \
        "{%0,%1,%2,%3},{%4,%5,%6,%7},{%8,%9},{%0,%1,%2,%3};" \
        : "+f"((C)[0]), "+f"((C)[1]), "+f"((C)[2]), "+f"((C)[3]) \
        : "r"((A)[0]), "r"((A)[1]), "r"((A)[2]), "r"((A)[3]), \
          "r"(b0), "r"(b1))

__device__ __forceinline__ unsigned smem_u32(const void* p) {
    unsigned a;
    asm("{ .reg .u64 t; cvta.to.shared.u64 t, %1; cvt.u32.u64 %0, t; }"
        : "=r"(a) : "l"(p));
    return a;
}
__device__ __forceinline__ unsigned short f2b(float x) {
    return __bfloat16_as_ushort(__float2bfloat16_rn(x));
}
__device__ __forceinline__ float b2f(unsigned short u) {
    return __bfloat162float(__ushort_as_bfloat16(u));
}

// Scratch
__device__ float g_keys_pre[Ntot * KD];
__device__ float g_alpha[Bsz * 256];
__device__ __align__(16) unsigned short g_A[2 * Ntot * OPAD];
__device__ __align__(16) unsigned short g_B[65 * 2 * NJ * OPAD];
__device__ float g_part2[(size_t)NKG * Ntot * PP];

// ---------------------------------------------------------------------------
// Kernel AP: fused preprocessing + front slice of the dense zero-fill.
//   blocks 0..64   : kP role (one bf16 term at a time -> 24KB pool)
//   blocks 65..320 : kA role — GAT, keys_pre, alpha, A bf16 terms
// ---------------------------------------------------------------------------
__global__ __launch_bounds__(288) void kAP(const float* __restrict__ aq,
                                           const float* __restrict__ obs,
                                           const float* __restrict__ Wg,
                                           const float* __restrict__ bg,
                                           const float* __restrict__ asrc,
                                           const float* __restrict__ adst,
                                           const float* __restrict__ Wh,
                                           float* __restrict__ dout) {
    __shared__ __align__(16) char pool[TERMB];   // 24192 BYTES
    int t = threadIdx.x;

    if (blockIdx.x < 65) {
        // ---------------- kP role: one term at a time ----------------
        unsigned short* Bs = (unsigned short*)pool;   // [72][168]
        int k = blockIdx.x;
        int j = t % NJ, oq = t / NJ;

        #pragma unroll
        for (int term = 0; term < 2; term++) {
            for (int i = 0; i < 40; i++) {
                int o = oq * 40 + i;
                float x = (j < KD) ? Wh[(size_t)o * KDSQ + k * KD + j] : 0.f;
                unsigned short v;
                if (term == 0) v = f2b(x);
                else           v = f2b(x - b2f(f2b(x)));
                Bs[j * OPAD + o] = v;
            }
            for (int idx = t; idx < NJ * 8; idx += 288) {
                int jj = idx >> 3, o = 160 + (idx & 7);
                Bs[jj * OPAD + o] = 0;
            }
            __syncthreads();
            uint4* dst = (uint4*)((char*)g_B + (size_t)k * SLABB + term * TERMB);
            const uint4* src = (const uint4*)Bs;
            for (int idx = t; idx < TERMB / 16; idx += 288) dst[idx] = src[idx];
            __syncthreads();
        }
    } else {
        // ---------------- kA role ---------------- (17408 B of pool)
        float* obs_s = (float*)pool;                    // [16][160]
        float* h_s   = obs_s + 16 * OB;                 // [16][64]
        float* sc_s  = h_s + 16 * GD;                   // [2][16][4]
        float* al    = sc_s + 128;                      // [2][8][8][4]
        float* aw    = al + 512;                        // [2][8][8]

        int bx = blockIdx.x - 65;
        int n0 = bx * 16;

        {
            const float4* src = (const float4*)(obs + (size_t)n0 * OB);
            float4* dst = (float4*)obs_s;
            for (int idx = t; idx < 16 * OB / 4; idx += 288) dst[idx] = src[idx];
        }
        __syncthreads();

        for (int idx = t; idx < 16 * OPAD; idx += 288) {
            int r = idx / OPAD, o = idx - r * OPAD;
            float x = (o < OB) ? obs_s[r * OB + o] : 0.f;
            unsigned short b1 = f2b(x);
            g_A[(size_t)(n0 + r) * OPAD + o] = b1;
            g_A[(size_t)Ntot * OPAD + (size_t)(n0 + r) * OPAD + o] =
                f2b(x - b2f(b1));
        }

        if (t < 256) {
            int r = t >> 4, gq = t & 15;
            float4 b4 = *(const float4*)(bg + gq * 4);
            float h0 = b4.x, h1 = b4.y, h2 = b4.z, h3 = b4.w;
            #pragma unroll 8
            for (int o = 0; o < OB; o++) {
                float x = obs_s[r * OB + o];
                float4 w = *(const float4*)(Wg + o * GD + gq * 4);
                h0 += x * w.x; h1 += x * w.y; h2 += x * w.z; h3 += x * w.w;
            }
            h_s[r * GD + gq * 4 + 0] = h0; h_s[r * GD + gq * 4 + 1] = h1;
            h_s[r * GD + gq * 4 + 2] = h2; h_s[r * GD + gq * 4 + 3] = h3;
        }
        __syncthreads();

        if (t < 128) {
            int a = t >> 3, hh = (t >> 1) & 3, sd = t & 1;
            const float* av = (sd ? adst : asrc) + hh * GD;
            float acc = 0.f;
            #pragma unroll 8
            for (int g = 0; g < GD; g++) acc += h_s[a * GD + g] * av[g];
            sc_s[(sd * 16 + a) * 4 + hh] = acc;
        }
        __syncthreads();

        if (t < 64) {
            int bbx = t >> 5, j = (t >> 2) & 7, hh = t & 3;
            float e[NA]; float m = -1e30f;
            #pragma unroll
            for (int i = 0; i < NA; i++) {
                if (i == j) { e[i] = -1e30f; continue; }
                float x = sc_s[(0 * 16 + bbx * 8 + i) * 4 + hh] +
                          sc_s[(1 * 16 + bbx * 8 + j) * 4 + hh];
                x = x > 0.f ? x : 0.2f * x;
                e[i] = x; m = fmaxf(m, x);
            }
            float s = 0.f;
            #pragma unroll
            for (int i = 0; i < NA; i++) {
                float ex = (i == j) ? 0.f : expf(e[i] - m);
                e[i] = ex; s += ex;
            }
            float inv = 1.f / (s + 1e-16f);
            #pragma unroll
            for (int i = 0; i < NA; i++)
                al[((bbx * 8 + i) * 8 + j) * 4 + hh] = e[i] * inv;
        }
        __syncthreads();

        for (int idx = t; idx < 512; idx += 288)
            g_alpha[(size_t)bx * 512 + idx] = al[idx];
        if (t < 128) {
            int bbx = t >> 6, i = (t >> 3) & 7, j = t & 7;
            const float* a4 = &al[((bbx * 8 + i) * 8 + j) * 4];
            aw[(bbx * 8 + i) * 8 + j] = a4[0] + a4[1] + a4[2] + a4[3];
        }
        __syncthreads();

        for (int idx = t; idx < 16 * GD; idx += 288) {
            int aa = idx >> 6, g = idx & 63;
            int bbx = aa >> 3, j = aa & 7;
            float acc = 0.f;
            #pragma unroll
            for (int i = 0; i < NA; i++)
                acc += h_s[(bbx * 8 + i) * GD + g] * aw[(bbx * 8 + i) * 8 + j];
            g_keys_pre[(size_t)(n0 + aa) * KD + 1 + g] = fmaxf(0.25f * acc, 0.f);
            if (g == 0)
                g_keys_pre[(size_t)(n0 + aa) * KD] = aq[n0 + aa];
        }
    }

    // ---- front slice of the dense zero-fill (all blocks) ----
    {
        float4* zp = (float4*)(dout + OUT_DENSE);
        unsigned long long zi = (unsigned long long)blockIdx.x * 288 + t;
        const float4 zero4 = make_float4(0.f, 0.f, 0.f, 0.f);
        #pragma unroll 4
        for (int z = 0; z < ZAP_PER; z++) {
            __stcs(&zp[zi], zero4);          // zi < Z_SPLIT by construction
            zi += ZAP_THREADS;
        }
    }
}

// ---------------------------------------------------------------------------
// Kernel B: bf16 mma.sync GEMM, split-2, N=72, pass-fused inner loop,
// fused keys*|.+bias| epilogue + k-group reduction; rear slice of zero-fill.
// ---------------------------------------------------------------------------
__global__ __launch_bounds__(256, 1) void kB(const float* __restrict__ bh,
                                             const float* __restrict__ keys_pre,
                                             float* __restrict__ dout) {
    extern __shared__ char sm[];
    unsigned sbase = smem_u32(sm);
    float* keys_s = (float*)(sm + SM_KEYS);
    float* bias_s = (float*)(sm + SM_BIAS);

    int bx = blockIdx.x;
    int kg = bx >> 5;
    int nt = bx & 31;
    int n0 = nt * 128;
    int k0 = kg * KPG;
    int t = threadIdx.x;
    int w = t >> 5, lane = t & 31;
    int gID = lane >> 2, tig = lane & 3;

    // ---- stage A terms ----
    {
        const char* gA = (const char*)g_A;
        #pragma unroll
        for (int rep = 0; rep < 21; rep++) {
            int idx = rep * 256 + t;
            int tr = idx / 21, chx = idx - tr * 21;
            int term = tr >> 7, row = tr & 127;
            const char* src = gA +
                ((size_t)term * Ntot + n0 + row) * (OPAD * 2) + chx * 16;
            CPA16(sbase + term * ATERM + row * 336 + chx * 16, src);
        }
        CPA_COMMIT();
    }
    // ---- stage B slab k0 ----
    {
        const char* src = (const char*)g_B + (size_t)k0 * SLABB;
        #pragma unroll
        for (int rep = 0; rep < 12; rep++) {
            int idx = rep * 256 + t;
            if (idx < SLABB / 16) CPA16(sbase + SM_B + idx * 16, src + idx * 16);
        }
        CPA_COMMIT();
    }
    for (int idx = t; idx < KPG * 128; idx += 256) {
        int kk = idx >> 7, r = idx & 127;
        keys_s[idx] = keys_pre[(size_t)(n0 + r) * KD + k0 + kk];
    }
    for (int idx = t; idx < KPG * NJ; idx += 256) {
        int kk = idx / NJ, j = idx - kk * NJ;
        bias_s[idx] = (j < KD) ? bh[(k0 + kk) * KD + j] : 0.f;
    }

    CPA_WAIT(1);
    __syncthreads();

    // ---- load A fragments ----
    unsigned aU[2][10][4];
    {
        int rbase = (w * 16 + gID) * 336;
        #pragma unroll
        for (int term = 0; term < 2; term++)
            #pragma unroll
            for (int c = 0; c < 10; c++) {
                const char* p = sm + term * ATERM + rbase + tig * 4 + c * 32;
                aU[term][c][0] = *(const unsigned*)(p);
                aU[term][c][1] = *(const unsigned*)(p + 8 * 336);
                aU[term][c][2] = *(const unsigned*)(p + 16);
                aU[term][c][3] = *(const unsigned*)(p + 8 * 336 + 16);
            }
    }

    // rear-slice zero-fill state
    float4* zp = (float4*)(dout + OUT_DENSE);
    unsigned long long zi = Z_SPLIT + (unsigned long long)bx * 256 + t;
    const unsigned long long zstride = (unsigned long long)GRIDB * 256;
    const float4 zero4 = make_float4(0.f, 0.f, 0.f, 0.f);

    float accv[9][4];
    #pragma unroll
    for (int n = 0; n < 9; n++)
        #pragma unroll
        for (int q = 0; q < 4; q++) accv[n][q] = 0.f;

    for (int kk = 0; kk < KPG; kk++) {
        if (kk < KPG - 1) {
            const char* src = (const char*)g_B + (size_t)(k0 + kk + 1) * SLABB;
            unsigned dst = sbase + SM_B + ((kk + 1) & 1) * SLABB;
            #pragma unroll
            for (int rep = 0; rep < 12; rep++) {
                int idx = rep * 256 + t;
                if (idx < SLABB / 16) CPA16(dst + idx * 16, src + idx * 16);
            }
            CPA_COMMIT();
            CPA_WAIT(1);
        } else {
            CPA_WAIT(0);
        }
        __syncthreads();

        float Cr[9][4];
        #pragma unroll
        for (int n = 0; n < 9; n++)
            #pragma unroll
            for (int q = 0; q < 4; q++) Cr[n][q] = 0.f;

        const char* bufb = sm + SM_B + (kk & 1) * SLABB + gID * 336 + tig * 4;
        #pragma unroll
        for (int c = 0; c < 10; c++) {
            #pragma unroll
            for (int n = 0; n < 9; n++) {
                const char* q0 = bufb + n * (8 * 336) + c * 32;   // term0
                unsigned b0 = *(const unsigned*)(q0);
                unsigned b1 = *(const unsigned*)(q0 + 16);
                MMA(Cr[n], aU[0][c], b0, b1);       // a1*b1
                MMA(Cr[n], aU[1][c], b0, b1);       // a2*b1
                const char* q1 = q0 + TERMB;                      // term1
                unsigned d0 = *(const unsigned*)(q1);
                unsigned d1 = *(const unsigned*)(q1 + 16);
                MMA(Cr[n], aU[0][c], d0, d1);       // a1*b2
            }
        }

        // rear-slice zero-fill (20 per kk)
        #pragma unroll
        for (int z = 0; z < 20; z++) {
            if (zi < DENSE_F4) __stcs(&zp[zi], zero4);
            zi += zstride;
        }

        // fused epilogue
        float k0v = keys_s[kk * 128 + w * 16 + gID];
        float k1v = keys_s[kk * 128 + w * 16 + gID + 8];
        const float* bs = bias_s + kk * NJ;
        #pragma unroll
        for (int n = 0; n < 9; n++) {
            int j0 = n * 8 + tig * 2;
            float b0s = bs[j0], b1s = bs[j0 + 1];
            accv[n][0] += k0v * fabsf(Cr[n][0] + b0s);
            accv[n][1] += k0v * fabsf(Cr[n][1] + b1s);
            accv[n][2] += k1v * fabsf(Cr[n][2] + b0s);
            accv[n][3] += k1v * fabsf(Cr[n][3] + b1s);
        }
        __syncthreads();
    }

    // write fused k-group partials
    {
        int r0 = n0 + w * 16 + gID;
        float* gp0 = g_part2 + ((size_t)kg * Ntot + r0) * PP;
        float* gp1 = gp0 + (size_t)8 * PP;
        #pragma unroll
        for (int n = 0; n < 8; n++) {
            int j0 = n * 8 + tig * 2;
            *(float2*)(gp0 + j0) = make_float2(accv[n][0], accv[n][1]);
            *(float2*)(gp1 + j0) = make_float2(accv[n][2], accv[n][3]);
        }
        if (tig == 0) {
            *(float2*)(gp0 + 64) = make_float2(accv[8][0], accv[8][1]);
            *(float2*)(gp1 + 64) = make_float2(accv[8][2], accv[8][3]);
        }
    }
}

// ---------------------------------------------------------------------------
// Kernel C: fused k-group reduction + elu + attention mixer, head weights,
// V, q_tot, alpha scatter.
// ---------------------------------------------------------------------------
__global__ __launch_bounds__(128) void kC(const float* __restrict__ aq,
                                          const float* __restrict__ states,
                                          const float* __restrict__ Wq,
                                          const float* __restrict__ Wk,
                                          const float* __restrict__ Wv1,
                                          const float* __restrict__ bv1,
                                          const float* __restrict__ Wv2,
                                          const float* __restrict__ bv2,
                                          const float* __restrict__ Ww1,
                                          const float* __restrict__ bw1,
                                          const float* __restrict__ Ww2,
                                          const float* __restrict__ bw2,
                                          float* __restrict__ dout) {
    int b = blockIdx.x, t = threadIdx.x;
    __shared__ float st_s[SD];
    __shared__ float keys_s[NA * KD];
    __shared__ float kvec[NA][NU];
    __shared__ float q_s[NU];
    __shared__ float hid[64], hv[32];
    __shared__ float hw_s[NH], v_s;
    __shared__ float outh[NH];

    for (int i = t; i < SD; i += 128) st_s[i] = states[(size_t)b * SD + i];

    const size_t KS = (size_t)Ntot * PP;
    for (int idx = t; idx < NA * KD; idx += 128) {
        int a = idx / KD, j = idx - a * KD;
        const float* p = g_part2 + (size_t)(b * NA + a) * PP + j;
        float s = 0.f;
        #pragma unroll
        for (int kg = 0; kg < NKG; kg++) s += p[(size_t)kg * KS];
        keys_s[idx] = (s > 0.f) ? s : expm1f(s);
    }
    __syncthreads();

    for (int idx = t; idx < NA * NU; idx += 128) {
        int a = idx / NU, u = idx & 31;
        float s = 0.f;
        #pragma unroll 5
        for (int j = 0; j < KD; j++) s += keys_s[a * KD + j] * Wk[j * NU + u];
        kvec[a][u] = s;
    }
    if (t < NU) {
        float s = 0.f;
        for (int o = 0; o < SD; o++) s += st_s[o] * Wq[o * NU + t];
        q_s[t] = s;
    } else if (t < 96) {
        int x = t - 32;
        float s = bw1[x];
        for (int o = 0; o < SD; o++) s += st_s[o] * Ww1[o * 64 + x];
        hid[x] = fmaxf(s, 0.f);
    } else {
        int x = t - 96;
        float s = bv1[x];
        for (int o = 0; o < SD; o++) s += st_s[o] * Wv1[o * NU + x];
        hv[x] = fmaxf(s, 0.f);
    }
    __syncthreads();

    if (t < NH) {
        float s = bw2[t];
        #pragma unroll
        for (int x = 0; x < 64; x++) s += hid[x] * Ww2[x * NH + t];
        hw_s[t] = s * s;
    } else if (t == NH) {
        float s = bv2[0];
        #pragma unroll
        for (int x = 0; x < 32; x++) s += hv[x] * Wv2[x];
        v_s = s;
    }
    __syncthreads();

    if (t < NH) {
        int hh = t;
        float sc[NA]; float m = -1e30f;
        #pragma unroll
        for (int a = 0; a < NA; a++) {
            float s = 0.f;
            #pragma unroll
            for (int dd = 0; dd < 8; dd++)
                s += q_s[hh * 8 + dd] * kvec[a][hh * 8 + dd];
            s *= 0.35355339059327373f;
            sc[a] = s; m = fmaxf(m, s);
        }
        float sum = 0.f;
        #pragma unroll
        for (int a = 0; a < NA; a++) { sc[a] = expf(sc[a] - m); sum += sc[a]; }
        float inv = 1.f / sum;
        float oh = 0.f;
        #pragma unroll
        for (int a = 0; a < NA; a++) {
            float at = sc[a] * inv;
            dout[OUT_ATTN + b * 32 + hh * 8 + a] = at;
            oh += at * aq[b * NA + a];
        }
        outh[hh] = oh * hw_s[hh];
    }
    __syncthreads();
    if (t == 0) dout[b] = outh[0] + outh[1] + outh[2] + outh[3] + v_s;

    for (int idx = t; idx < 256; idx += 128) {
        int i = idx >> 5, j = (idx >> 2) & 7, hh = idx & 3;
        dout[OUT_DENSE +
             (((size_t)(b * NA + i)) * Ntot + b * NA + j) * NH + hh] =
            g_alpha[b * 256 + idx];
    }
}

// ---------------------------------------------------------------------------
extern "C" void kernel_launch(void* const* d_in, const int* in_sizes, int n_in,
                              void* d_out, int out_size) {
    const float* aq     = (const float*)d_in[0];
    const float* obs    = (const float*)d_in[1];
    const float* states = (const float*)d_in[2];
    // d_in[3] = edge_index (deterministic; unused)
    const float* Wg   = (const float*)d_in[4];
    const float* bg   = (const float*)d_in[5];
    const float* asrc = (const float*)d_in[6];
    const float* adst = (const float*)d_in[7];
    const float* Wh   = (const float*)d_in[8];
    const float* bh   = (const float*)d_in[9];
    const float* Wq   = (const float*)d_in[10];
    const float* Wk   = (const float*)d_in[11];
    const float* Wv1  = (const float*)d_in[12];
    const float* bv1  = (const float*)d_in[13];
    const float* Wv2  = (const float*)d_in[14];
    const float* bv2  = (const float*)d_in[15];
    const float* Ww1  = (const float*)d_in[16];
    const float* bw1  = (const float*)d_in[17];
    const float* Ww2  = (const float*)d_in[18];
    const float* bw2  = (const float*)d_in[19];
    float* out = (float*)d_out;

    cudaFuncSetAttribute(kB, cudaFuncAttributeMaxDynamicSharedMemorySize,
                         SM_TOT);

    float* keys_pre_ptr;
    cudaGetSymbolAddress((void**)&keys_pre_ptr, g_keys_pre);

    kAP<<<321, 288>>>(aq, obs, Wg, bg, asrc, adst, Wh, out);
    kB<<<GRIDB, 256, SM_TOT>>>(bh, keys_pre_ptr, out);
    kC<<<Bsz, 128>>>(aq, states, Wq, Wk, Wv1, bv1, Wv2, bv2,
                     Ww1, bw1, Ww2, bw2, out);
}

// round 17
// speedup vs baseline: 1.0731x; 1.0731x over previous
#include <cuda_runtime.h>
#include <cuda_bf16.h>
#include <math.h>

// Problem constants
#define Bsz   512
#define NA    8
#define OB    160
#define SD    256
#define NH    4
#define GD    64
#define KD    65
#define NU    32
#define Ntot  4096
#define KDSQ  4225

// Output layout (flat concat, fp32)
#define OUT_ATTN  512
#define OUT_DENSE 16896
#define DENSE_F4  16777216ULL

#define PP 68              // g_part2 pitch

// kB geometry
#define NKG    13
#define KPG    5
#define NTIL   32
#define OPAD   168         // padded o-dim (336B rows)
#define NJ     72          // padded j-dim (j=64 real, 65..71 zero)
#define SLABB  48384       // one k B slab BYTES
#define TERMB  24192       // one B term (72 j x 336B)
#define ATERM  43008       // one A term (128 rows x 336B)
#define GRIDB  (NKG * NTIL)   // 416
// kB smem: A [0,86016) | B double buffer [86016,182784) | keys | bias
#define SM_B    86016
#define SM_KEYS 182784
#define SM_BIAS 185344
#define SM_TOT  186880

#define CPA16(dst, src) asm volatile("cp.async.cg.shared.global [%0], [%1], 16;" :: "r"(dst), "l"(src))
#define CPA_COMMIT() asm volatile("cp.async.commit_group;")
#define CPA_WAIT(n)  asm volatile("cp.async.wait_group %0;" :: "n"(n))
#define MMA(C, A, b0, b1) \
    asm volatile("mma.sync.aligned.m16n8k16.row.col.f32.bf16.bf16.f32 " \
        "{%0,%1,%2,%3},{%4,%5,%6,%7},{%8,%9},{%0,%1,%2,%3};" \
        : "+f"((C)[0]), "+f"((C)[1]), "+f"((C)[2]), "+f"((C)[3]) \
        : "r"((A)[0]), "r"((A)[1]), "r"((A)[2]), "r"((A)[3]), \
          "r"(b0), "r"(b1))

__device__ __forceinline__ unsigned smem_u32(const void* p) {
    unsigned a;
    asm("{ .reg .u64 t; cvta.to.shared.u64 t, %1; cvt.u32.u64 %0, t; }"
        : "=r"(a) : "l"(p));
    return a;
}
__device__ __forceinline__ unsigned short f2b(float x) {
    return __bfloat16_as_ushort(__float2bfloat16_rn(x));
}
__device__ __forceinline__ float b2f(unsigned short u) {
    return __bfloat162float(__ushort_as_bfloat16(u));
}

// Scratch
__device__ float g_keys_pre[Ntot * KD];
__device__ float g_alpha[Bsz * 256];
__device__ __align__(16) unsigned short g_A[2 * Ntot * OPAD];
__device__ __align__(16) unsigned short g_B[65 * 2 * NJ * OPAD];
__device__ float g_part2[(size_t)NKG * Ntot * PP];

// ---------------------------------------------------------------------------
// Kernel AP: fused preprocessing.
//   blocks 0..64   : kP role — split W_h slab k into 2 bf16 terms -> g_B
//   blocks 65..576 : kA role — GAT (ONE batch = 8 agents per block)
// ---------------------------------------------------------------------------
__global__ __launch_bounds__(288) void kAP(const float* __restrict__ aq,
                                           const float* __restrict__ obs,
                                           const float* __restrict__ Wg,
                                           const float* __restrict__ bg,
                                           const float* __restrict__ asrc,
                                           const float* __restrict__ adst,
                                           const float* __restrict__ Wh) {
    __shared__ __align__(16) char pool[SLABB];   // 48384 BYTES
    int t = threadIdx.x;

    if (blockIdx.x < 65) {
        // ---------------- kP role (two terms, 48KB pool) ----------------
        unsigned short* Bs = (unsigned short*)pool;   // 2*NJ*OPAD shorts
        int k = blockIdx.x;
        int j = t % NJ, oq = t / NJ;

        for (int i = 0; i < 40; i++) {
            int o = oq * 40 + i;
            float x = (j < KD) ? Wh[(size_t)o * KDSQ + k * KD + j] : 0.f;
            unsigned short b1 = f2b(x);
            unsigned short b2 = f2b(x - b2f(b1));
            Bs[j * OPAD + o] = b1;
            Bs[NJ * OPAD + j * OPAD + o] = b2;
        }
        for (int idx = t; idx < 2 * NJ * 8; idx += 288) {
            int term = idx / (NJ * 8), rem = idx % (NJ * 8);
            int jj = rem >> 3, o = 160 + (rem & 7);
            Bs[term * NJ * OPAD + jj * OPAD + o] = 0;
        }
        __syncthreads();
        uint4* dst = (uint4*)((char*)g_B + (size_t)k * SLABB);
        const uint4* src = (const uint4*)Bs;
        for (int idx = t; idx < SLABB / 16; idx += 288) dst[idx] = src[idx];
        return;
    }

    // ---------------- kA role: ONE batch (8 agents), 8704 B of pool ------
    float* obs_s = (float*)pool;                    // [8][160]
    float* h_s   = obs_s + 8 * OB;                  // [8][64]
    float* sc_s  = h_s + 8 * GD;                    // [2][8][4]
    float* al    = sc_s + 64;                       // [8][8][4] = 256
    float* aw    = al + 256;                        // [8][8]

    int bx = blockIdx.x - 65;                       // 0..511 (= batch b)
    int n0 = bx * 8;

    {
        const float4* src = (const float4*)(obs + (size_t)n0 * OB);
        float4* dst = (float4*)obs_s;
        for (int idx = t; idx < 8 * OB / 4; idx += 288) dst[idx] = src[idx];
    }
    __syncthreads();

    // A bf16 terms (padded to OPAD)
    for (int idx = t; idx < 8 * OPAD; idx += 288) {
        int r = idx / OPAD, o = idx - r * OPAD;
        float x = (o < OB) ? obs_s[r * OB + o] : 0.f;
        unsigned short b1 = f2b(x);
        g_A[(size_t)(n0 + r) * OPAD + o] = b1;
        g_A[(size_t)Ntot * OPAD + (size_t)(n0 + r) * OPAD + o] =
            f2b(x - b2f(b1));
    }

    // h = obs @ W_gnn + b : 128 threads = (row r, col-quad gq)
    if (t < 128) {
        int r = t >> 4, gq = t & 15;
        float4 b4 = *(const float4*)(bg + gq * 4);
        float h0 = b4.x, h1 = b4.y, h2 = b4.z, h3 = b4.w;
        #pragma unroll 8
        for (int o = 0; o < OB; o++) {
            float x = obs_s[r * OB + o];
            float4 w = *(const float4*)(Wg + o * GD + gq * 4);
            h0 += x * w.x; h1 += x * w.y; h2 += x * w.z; h3 += x * w.w;
        }
        h_s[r * GD + gq * 4 + 0] = h0; h_s[r * GD + gq * 4 + 1] = h1;
        h_s[r * GD + gq * 4 + 2] = h2; h_s[r * GD + gq * 4 + 3] = h3;
    }
    __syncthreads();

    // src/dst scores: 8 agents x 4 heads x 2 = 64 threads
    if (t < 64) {
        int a = t >> 3, hh = (t >> 1) & 3, sd = t & 1;
        const float* av = (sd ? adst : asrc) + hh * GD;
        float acc = 0.f;
        #pragma unroll 8
        for (int g = 0; g < GD; g++) acc += h_s[a * GD + g] * av[g];
        sc_s[(sd * 8 + a) * 4 + hh] = acc;
    }
    __syncthreads();

    // alpha per (dst j, head) : 32 threads
    if (t < 32) {
        int j = t >> 2, hh = t & 3;
        float e[NA]; float m = -1e30f;
        #pragma unroll
        for (int i = 0; i < NA; i++) {
            if (i == j) { e[i] = -1e30f; continue; }
            float x = sc_s[(0 * 8 + i) * 4 + hh] + sc_s[(1 * 8 + j) * 4 + hh];
            x = x > 0.f ? x : 0.2f * x;
            e[i] = x; m = fmaxf(m, x);
        }
        float s = 0.f;
        #pragma unroll
        for (int i = 0; i < NA; i++) {
            float ex = (i == j) ? 0.f : expf(e[i] - m);
            e[i] = ex; s += ex;
        }
        float inv = 1.f / (s + 1e-16f);
        #pragma unroll
        for (int i = 0; i < NA; i++)
            al[(i * 8 + j) * 4 + hh] = e[i] * inv;
    }
    __syncthreads();

    // dump alpha + head-summed weights
    if (t < 256)
        g_alpha[(size_t)bx * 256 + t] = al[t];
    if (t < 64) {
        int i = t >> 3, j = t & 7;
        const float* a4 = &al[(i * 8 + j) * 4];
        aw[i * 8 + j] = a4[0] + a4[1] + a4[2] + a4[3];
    }
    __syncthreads();

    // agg + relu -> keys_pre
    for (int idx = t; idx < 8 * GD; idx += 288) {
        int aa = idx >> 6, g = idx & 63;
        float acc = 0.f;
        #pragma unroll
        for (int i = 0; i < NA; i++)
            acc += h_s[i * GD + g] * aw[i * 8 + aa];
        g_keys_pre[(size_t)(n0 + aa) * KD + 1 + g] = fmaxf(0.25f * acc, 0.f);
        if (g == 0)
            g_keys_pre[(size_t)(n0 + aa) * KD] = aq[n0 + aa];
    }
}

// ---------------------------------------------------------------------------
// Kernel B: bf16 mma.sync GEMM, split-2, N=72, pass-fused inner loop,
// fused keys*|.+bias| epilogue + k-group reduction; full hidden zero-fill.
// ---------------------------------------------------------------------------
__global__ __launch_bounds__(256, 1) void kB(const float* __restrict__ bh,
                                             const float* __restrict__ keys_pre,
                                             float* __restrict__ dout) {
    extern __shared__ char sm[];
    unsigned sbase = smem_u32(sm);
    float* keys_s = (float*)(sm + SM_KEYS);
    float* bias_s = (float*)(sm + SM_BIAS);

    int bx = blockIdx.x;
    int kg = bx >> 5;
    int nt = bx & 31;
    int n0 = nt * 128;
    int k0 = kg * KPG;
    int t = threadIdx.x;
    int w = t >> 5, lane = t & 31;
    int gID = lane >> 2, tig = lane & 3;

    // ---- stage A terms ----
    {
        const char* gA = (const char*)g_A;
        #pragma unroll
        for (int rep = 0; rep < 21; rep++) {
            int idx = rep * 256 + t;
            int tr = idx / 21, chx = idx - tr * 21;
            int term = tr >> 7, row = tr & 127;
            const char* src = gA +
                ((size_t)term * Ntot + n0 + row) * (OPAD * 2) + chx * 16;
            CPA16(sbase + term * ATERM + row * 336 + chx * 16, src);
        }
        CPA_COMMIT();
    }
    // ---- stage B slab k0 ----
    {
        const char* src = (const char*)g_B + (size_t)k0 * SLABB;
        #pragma unroll
        for (int rep = 0; rep < 12; rep++) {
            int idx = rep * 256 + t;
            if (idx < SLABB / 16) CPA16(sbase + SM_B + idx * 16, src + idx * 16);
        }
        CPA_COMMIT();
    }
    for (int idx = t; idx < KPG * 128; idx += 256) {
        int kk = idx >> 7, r = idx & 127;
        keys_s[idx] = keys_pre[(size_t)(n0 + r) * KD + k0 + kk];
    }
    for (int idx = t; idx < KPG * NJ; idx += 256) {
        int kk = idx / NJ, j = idx - kk * NJ;
        bias_s[idx] = (j < KD) ? bh[(k0 + kk) * KD + j] : 0.f;
    }

    CPA_WAIT(1);
    __syncthreads();

    // ---- load A fragments ----
    unsigned aU[2][10][4];
    {
        int rbase = (w * 16 + gID) * 336;
        #pragma unroll
        for (int term = 0; term < 2; term++)
            #pragma unroll
            for (int c = 0; c < 10; c++) {
                const char* p = sm + term * ATERM + rbase + tig * 4 + c * 32;
                aU[term][c][0] = *(const unsigned*)(p);
                aU[term][c][1] = *(const unsigned*)(p + 8 * 336);
                aU[term][c][2] = *(const unsigned*)(p + 16);
                aU[term][c][3] = *(const unsigned*)(p + 8 * 336 + 16);
            }
    }

    // zero-fill state (full region)
    float4* zp = (float4*)(dout + OUT_DENSE);
    unsigned long long zi = (unsigned long long)bx * 256 + t;
    const unsigned long long zstride = (unsigned long long)GRIDB * 256;
    const float4 zero4 = make_float4(0.f, 0.f, 0.f, 0.f);

    float accv[9][4];
    #pragma unroll
    for (int n = 0; n < 9; n++)
        #pragma unroll
        for (int q = 0; q < 4; q++) accv[n][q] = 0.f;

    for (int kk = 0; kk < KPG; kk++) {
        if (kk < KPG - 1) {
            const char* src = (const char*)g_B + (size_t)(k0 + kk + 1) * SLABB;
            unsigned dst = sbase + SM_B + ((kk + 1) & 1) * SLABB;
            #pragma unroll
            for (int rep = 0; rep < 12; rep++) {
                int idx = rep * 256 + t;
                if (idx < SLABB / 16) CPA16(dst + idx * 16, src + idx * 16);
            }
            CPA_COMMIT();
            CPA_WAIT(1);
        } else {
            CPA_WAIT(0);
        }
        __syncthreads();

        float Cr[9][4];
        #pragma unroll
        for (int n = 0; n < 9; n++)
            #pragma unroll
            for (int q = 0; q < 4; q++) Cr[n][q] = 0.f;

        const char* bufb = sm + SM_B + (kk & 1) * SLABB + gID * 336 + tig * 4;
        #pragma unroll
        for (int c = 0; c < 10; c++) {
            #pragma unroll
            for (int n = 0; n < 9; n++) {
                const char* q0 = bufb + n * (8 * 336) + c * 32;   // term0
                unsigned b0 = *(const unsigned*)(q0);
                unsigned b1 = *(const unsigned*)(q0 + 16);
                MMA(Cr[n], aU[0][c], b0, b1);       // a1*b1
                MMA(Cr[n], aU[1][c], b0, b1);       // a2*b1
                const char* q1 = q0 + TERMB;                      // term1
                unsigned d0 = *(const unsigned*)(q1);
                unsigned d1 = *(const unsigned*)(q1 + 16);
                MMA(Cr[n], aU[0][c], d0, d1);       // a1*b2
            }
        }

        // hidden zero-fill (32 per kk)
        #pragma unroll
        for (int z = 0; z < 32; z++) {
            if (zi < DENSE_F4) __stcs(&zp[zi], zero4);
            zi += zstride;
        }

        // fused epilogue
        float k0v = keys_s[kk * 128 + w * 16 + gID];
        float k1v = keys_s[kk * 128 + w * 16 + gID + 8];
        const float* bs = bias_s + kk * NJ;
        #pragma unroll
        for (int n = 0; n < 9; n++) {
            int j0 = n * 8 + tig * 2;
            float b0s = bs[j0], b1s = bs[j0 + 1];
            accv[n][0] += k0v * fabsf(Cr[n][0] + b0s);
            accv[n][1] += k0v * fabsf(Cr[n][1] + b1s);
            accv[n][2] += k1v * fabsf(Cr[n][2] + b0s);
            accv[n][3] += k1v * fabsf(Cr[n][3] + b1s);
        }
        __syncthreads();
    }

    // write fused k-group partials
    {
        int r0 = n0 + w * 16 + gID;
        float* gp0 = g_part2 + ((size_t)kg * Ntot + r0) * PP;
        float* gp1 = gp0 + (size_t)8 * PP;
        #pragma unroll
        for (int n = 0; n < 8; n++) {
            int j0 = n * 8 + tig * 2;
            *(float2*)(gp0 + j0) = make_float2(accv[n][0], accv[n][1]);
            *(float2*)(gp1 + j0) = make_float2(accv[n][2], accv[n][3]);
        }
        if (tig == 0) {
            *(float2*)(gp0 + 64) = make_float2(accv[8][0], accv[8][1]);
            *(float2*)(gp1 + 64) = make_float2(accv[8][2], accv[8][3]);
        }
    }
}

// ---------------------------------------------------------------------------
// Kernel C: fused k-group reduction + elu + attention mixer, head weights,
// V, q_tot, alpha scatter.
// ---------------------------------------------------------------------------
__global__ __launch_bounds__(128) void kC(const float* __restrict__ aq,
                                          const float* __restrict__ states,
                                          const float* __restrict__ Wq,
                                          const float* __restrict__ Wk,
                                          const float* __restrict__ Wv1,
                                          const float* __restrict__ bv1,
                                          const float* __restrict__ Wv2,
                                          const float* __restrict__ bv2,
                                          const float* __restrict__ Ww1,
                                          const float* __restrict__ bw1,
                                          const float* __restrict__ Ww2,
                                          const float* __restrict__ bw2,
                                          float* __restrict__ dout) {
    int b = blockIdx.x, t = threadIdx.x;
    __shared__ float st_s[SD];
    __shared__ float keys_s[NA * KD];
    __shared__ float kvec[NA][NU];
    __shared__ float q_s[NU];
    __shared__ float hid[64], hv[32];
    __shared__ float hw_s[NH], v_s;
    __shared__ float outh[NH];

    for (int i = t; i < SD; i += 128) st_s[i] = states[(size_t)b * SD + i];

    const size_t KS = (size_t)Ntot * PP;
    for (int idx = t; idx < NA * KD; idx += 128) {
        int a = idx / KD, j = idx - a * KD;
        const float* p = g_part2 + (size_t)(b * NA + a) * PP + j;
        float s = 0.f;
        #pragma unroll
        for (int kg = 0; kg < NKG; kg++) s += p[(size_t)kg * KS];
        keys_s[idx] = (s > 0.f) ? s : expm1f(s);
    }
    __syncthreads();

    for (int idx = t; idx < NA * NU; idx += 128) {
        int a = idx / NU, u = idx & 31;
        float s = 0.f;
        #pragma unroll 5
        for (int j = 0; j < KD; j++) s += keys_s[a * KD + j] * Wk[j * NU + u];
        kvec[a][u] = s;
    }
    if (t < NU) {
        float s = 0.f;
        for (int o = 0; o < SD; o++) s += st_s[o] * Wq[o * NU + t];
        q_s[t] = s;
    } else if (t < 96) {
        int x = t - 32;
        float s = bw1[x];
        for (int o = 0; o < SD; o++) s += st_s[o] * Ww1[o * 64 + x];
        hid[x] = fmaxf(s, 0.f);
    } else {
        int x = t - 96;
        float s = bv1[x];
        for (int o = 0; o < SD; o++) s += st_s[o] * Wv1[o * NU + x];
        hv[x] = fmaxf(s, 0.f);
    }
    __syncthreads();

    if (t < NH) {
        float s = bw2[t];
        #pragma unroll
        for (int x = 0; x < 64; x++) s += hid[x] * Ww2[x * NH + t];
        hw_s[t] = s * s;
    } else if (t == NH) {
        float s = bv2[0];
        #pragma unroll
        for (int x = 0; x < 32; x++) s += hv[x] * Wv2[x];
        v_s = s;
    }
    __syncthreads();

    if (t < NH) {
        int hh = t;
        float sc[NA]; float m = -1e30f;
        #pragma unroll
        for (int a = 0; a < NA; a++) {
            float s = 0.f;
            #pragma unroll
            for (int dd = 0; dd < 8; dd++)
                s += q_s[hh * 8 + dd] * kvec[a][hh * 8 + dd];
            s *= 0.35355339059327373f;
            sc[a] = s; m = fmaxf(m, s);
        }
        float sum = 0.f;
        #pragma unroll
        for (int a = 0; a < NA; a++) { sc[a] = expf(sc[a] - m); sum += sc[a]; }
        float inv = 1.f / sum;
        float oh = 0.f;
        #pragma unroll
        for (int a = 0; a < NA; a++) {
            float at = sc[a] * inv;
            dout[OUT_ATTN + b * 32 + hh * 8 + a] = at;
            oh += at * aq[b * NA + a];
        }
        outh[hh] = oh * hw_s[hh];
    }
    __syncthreads();
    if (t == 0) dout[b] = outh[0] + outh[1] + outh[2] + outh[3] + v_s;

    for (int idx = t; idx < 256; idx += 128) {
        int i = idx >> 5, j = (idx >> 2) & 7, hh = idx & 3;
        dout[OUT_DENSE +
             (((size_t)(b * NA + i)) * Ntot + b * NA + j) * NH + hh] =
            g_alpha[b * 256 + idx];
    }
}

// ---------------------------------------------------------------------------
extern "C" void kernel_launch(void* const* d_in, const int* in_sizes, int n_in,
                              void* d_out, int out_size) {
    const float* aq     = (const float*)d_in[0];
    const float* obs    = (const float*)d_in[1];
    const float* states = (const float*)d_in[2];
    // d_in[3] = edge_index (deterministic; unused)
    const float* Wg   = (const float*)d_in[4];
    const float* bg   = (const float*)d_in[5];
    const float* asrc = (const float*)d_in[6];
    const float* adst = (const float*)d_in[7];
    const float* Wh   = (const float*)d_in[8];
    const float* bh   = (const float*)d_in[9];
    const float* Wq   = (const float*)d_in[10];
    const float* Wk   = (const float*)d_in[11];
    const float* Wv1  = (const float*)d_in[12];
    const float* bv1  = (const float*)d_in[13];
    const float* Wv2  = (const float*)d_in[14];
    const float* bv2  = (const float*)d_in[15];
    const float* Ww1  = (const float*)d_in[16];
    const float* bw1  = (const float*)d_in[17];
    const float* Ww2  = (const float*)d_in[18];
    const float* bw2  = (const float*)d_in[19];
    float* out = (float*)d_out;

    cudaFuncSetAttribute(kB, cudaFuncAttributeMaxDynamicSharedMemorySize,
                         SM_TOT);

    float* keys_pre_ptr;
    cudaGetSymbolAddress((void**)&keys_pre_ptr, g_keys_pre);

    kAP<<<65 + Bsz, 288>>>(aq, obs, Wg, bg, asrc, adst, Wh);
    kB<<<GRIDB, 256, SM_TOT>>>(bh, keys_pre_ptr, out);
    kC<<<Bsz, 128>>>(aq, states, Wq, Wk, Wv1, bv1, Wv2, bv2,
                     Ww1, bw1, Ww2, bw2, out);
}